// round 1
// baseline (speedup 1.0000x reference)
#include <cuda_runtime.h>
#include <cstdint>

#define N_LEVELS 14
#define LOG2_T   19
#define T_MASK   ((1u << LOG2_T) - 1u)
#define TBL_SZ   (1u << LOG2_T)
#define WIDTH    64
#define D_IN     36
#define P1       2654435761u
#define P2       805459861u
#define NTHREADS 128

__device__ __forceinline__ float tanh_fast(float x) {
    float y;
    asm("tanh.approx.f32 %0, %1;" : "=f"(y) : "f"(x));
    return y;
}

__global__ void __launch_bounds__(NTHREADS)
deformnet_kernel(const float* __restrict__ x,
                 const float* __restrict__ e,
                 const float* __restrict__ tables,
                 const float* __restrict__ W1, const float* __restrict__ b1,
                 const float* __restrict__ W2, const float* __restrict__ b2,
                 const float* __restrict__ W3, const float* __restrict__ b3,
                 const float* __restrict__ bbox,
                 float* __restrict__ out, int n)
{
    // ---- stage weights in shared (broadcast reads in the MLP) ----
    __shared__ float sW1[D_IN * WIDTH];     // 2304
    __shared__ float sW2[WIDTH * WIDTH];    // 4096
    __shared__ float sW3[WIDTH * 3];        // 192
    __shared__ float sB1[WIDTH], sB2[WIDTH], sB3[3];
    __shared__ float sBB[6];

    for (int i = threadIdx.x; i < D_IN * WIDTH;  i += NTHREADS) sW1[i] = W1[i];
    for (int i = threadIdx.x; i < WIDTH * WIDTH; i += NTHREADS) sW2[i] = W2[i];
    for (int i = threadIdx.x; i < WIDTH * 3;     i += NTHREADS) sW3[i] = W3[i];
    if (threadIdx.x < WIDTH) { sB1[threadIdx.x] = b1[threadIdx.x]; sB2[threadIdx.x] = b2[threadIdx.x]; }
    if (threadIdx.x < 3)  sB3[threadIdx.x] = b3[threadIdx.x];
    if (threadIdx.x < 6)  sBB[threadIdx.x] = bbox[threadIdx.x];
    __syncthreads();

    int idx = blockIdx.x * NTHREADS + threadIdx.x;
    if (idx >= n) return;

    const float lo0 = sBB[0], lo1 = sBB[1], lo2 = sBB[2];
    const float hi0 = sBB[3], hi1 = sBB[4], hi2 = sBB[5];

    float xn0 = (x[idx * 3 + 0] - lo0) / (hi0 - lo0);
    float xn1 = (x[idx * 3 + 1] - lo1) / (hi1 - lo1);
    float xn2 = (x[idx * 3 + 2] - lo2) / (hi2 - lo2);

    // resolutions = floor(16 * 1.32^l), l = 0..13
    const float res_tab[N_LEVELS] = {16.f, 21.f, 27.f, 36.f, 48.f, 64.f, 84.f,
                                     111.f, 147.f, 194.f, 256.f, 339.f, 447.f, 590.f};

    float in[D_IN];

    const float2* __restrict__ tabs = (const float2*)tables;

    #pragma unroll
    for (int l = 0; l < N_LEVELS; l++) {
        const float r = res_tab[l];
        float px = xn0 * r, py = xn1 * r, pz = xn2 * r;
        float bx = floorf(px), by = floorf(py), bz = floorf(pz);
        float fx = px - bx, fy = py - by, fz = pz - bz;
        // smoothstep weights
        float wx = fx * fx * (3.f - 2.f * fx);
        float wy = fy * fy * (3.f - 2.f * fy);
        float wz = fz * fz * (3.f - 2.f * fz);

        unsigned ix = (unsigned)bx, iy = (unsigned)by, iz = (unsigned)bz;
        unsigned hx0 = ix,            hx1 = ix + 1u;           // prime 1
        unsigned hy0 = iy * P1,       hy1 = (iy + 1u) * P1;
        unsigned hz0 = iz * P2,       hz1 = (iz + 1u) * P2;

        const float2* __restrict__ tab = tabs + (size_t)l * TBL_SZ;

        float2 c000 = __ldg(&tab[(hx0 ^ hy0 ^ hz0) & T_MASK]);
        float2 c001 = __ldg(&tab[(hx0 ^ hy0 ^ hz1) & T_MASK]);
        float2 c010 = __ldg(&tab[(hx0 ^ hy1 ^ hz0) & T_MASK]);
        float2 c011 = __ldg(&tab[(hx0 ^ hy1 ^ hz1) & T_MASK]);
        float2 c100 = __ldg(&tab[(hx1 ^ hy0 ^ hz0) & T_MASK]);
        float2 c101 = __ldg(&tab[(hx1 ^ hy0 ^ hz1) & T_MASK]);
        float2 c110 = __ldg(&tab[(hx1 ^ hy1 ^ hz0) & T_MASK]);
        float2 c111 = __ldg(&tab[(hx1 ^ hy1 ^ hz1) & T_MASK]);

        float ux = 1.f - wx, uy = 1.f - wy, uz = 1.f - wz;
        float w00 = ux * uy, w01 = ux * wy, w10 = wx * uy, w11 = wx * wy;
        float w000 = w00 * uz, w001 = w00 * wz;
        float w010 = w01 * uz, w011 = w01 * wz;
        float w100 = w10 * uz, w101 = w10 * wz;
        float w110 = w11 * uz, w111 = w11 * wz;

        float a0, a1;
        a0 = w000 * c000.x; a1 = w000 * c000.y;
        a0 = fmaf(w001, c001.x, a0); a1 = fmaf(w001, c001.y, a1);
        a0 = fmaf(w010, c010.x, a0); a1 = fmaf(w010, c010.y, a1);
        a0 = fmaf(w011, c011.x, a0); a1 = fmaf(w011, c011.y, a1);
        a0 = fmaf(w100, c100.x, a0); a1 = fmaf(w100, c100.y, a1);
        a0 = fmaf(w101, c101.x, a0); a1 = fmaf(w101, c101.y, a1);
        a0 = fmaf(w110, c110.x, a0); a1 = fmaf(w110, c110.y, a1);
        a0 = fmaf(w111, c111.x, a0); a1 = fmaf(w111, c111.y, a1);
        in[2 * l + 0] = a0;
        in[2 * l + 1] = a1;
    }

    // extra features e [N, 8]
    {
        const float4* e4 = (const float4*)(e + (size_t)idx * 8);
        float4 ea = __ldg(&e4[0]);
        float4 eb = __ldg(&e4[1]);
        in[28] = ea.x; in[29] = ea.y; in[30] = ea.z; in[31] = ea.w;
        in[32] = eb.x; in[33] = eb.y; in[34] = eb.z; in[35] = eb.w;
    }

    // ---- layer 1: [36] -> [64], tanh ----
    float h1[WIDTH];
    #pragma unroll
    for (int j = 0; j < WIDTH; j += 4) {
        float4 acc = *(const float4*)&sB1[j];
        #pragma unroll
        for (int i = 0; i < D_IN; i++) {
            float4 w = *(const float4*)&sW1[i * WIDTH + j];
            acc.x = fmaf(in[i], w.x, acc.x);
            acc.y = fmaf(in[i], w.y, acc.y);
            acc.z = fmaf(in[i], w.z, acc.z);
            acc.w = fmaf(in[i], w.w, acc.w);
        }
        h1[j + 0] = tanh_fast(acc.x);
        h1[j + 1] = tanh_fast(acc.y);
        h1[j + 2] = tanh_fast(acc.z);
        h1[j + 3] = tanh_fast(acc.w);
    }

    // ---- layer 2: [64] -> [64], tanh ----
    float h2[WIDTH];
    #pragma unroll
    for (int j = 0; j < WIDTH; j += 4) {
        float4 acc = *(const float4*)&sB2[j];
        #pragma unroll
        for (int i = 0; i < WIDTH; i++) {
            float4 w = *(const float4*)&sW2[i * WIDTH + j];
            acc.x = fmaf(h1[i], w.x, acc.x);
            acc.y = fmaf(h1[i], w.y, acc.y);
            acc.z = fmaf(h1[i], w.z, acc.z);
            acc.w = fmaf(h1[i], w.w, acc.w);
        }
        h2[j + 0] = tanh_fast(acc.x);
        h2[j + 1] = tanh_fast(acc.y);
        h2[j + 2] = tanh_fast(acc.z);
        h2[j + 3] = tanh_fast(acc.w);
    }

    // ---- layer 3: [64] -> [3] ----
    float o0 = sB3[0], o1 = sB3[1], o2 = sB3[2];
    #pragma unroll
    for (int i = 0; i < WIDTH; i++) {
        float hv = h2[i];
        o0 = fmaf(hv, sW3[i * 3 + 0], o0);
        o1 = fmaf(hv, sW3[i * 3 + 1], o1);
        o2 = fmaf(hv, sW3[i * 3 + 2], o2);
    }

    // residual + rescale to bbox
    o0 = (o0 + xn0) * (hi0 - lo0) + lo0;
    o1 = (o1 + xn1) * (hi1 - lo1) + lo1;
    o2 = (o2 + xn2) * (hi2 - lo2) + lo2;

    out[idx * 3 + 0] = o0;
    out[idx * 3 + 1] = o1;
    out[idx * 3 + 2] = o2;
}

extern "C" void kernel_launch(void* const* d_in, const int* in_sizes, int n_in,
                              void* d_out, int out_size)
{
    const float* x      = (const float*)d_in[0];
    const float* e      = (const float*)d_in[1];
    const float* tables = (const float*)d_in[2];
    const float* W1     = (const float*)d_in[3];
    const float* b1     = (const float*)d_in[4];
    const float* W2     = (const float*)d_in[5];
    const float* b2     = (const float*)d_in[6];
    const float* W3     = (const float*)d_in[7];
    const float* b3     = (const float*)d_in[8];
    const float* bbox   = (const float*)d_in[9];
    float* out = (float*)d_out;

    int n = in_sizes[0] / 3;
    int grid = (n + NTHREADS - 1) / NTHREADS;
    deformnet_kernel<<<grid, NTHREADS>>>(x, e, tables, W1, b1, W2, b2, W3, b3, bbox, out, n);
}